// round 2
// baseline (speedup 1.0000x reference)
#include <cuda_runtime.h>

// Problem constants
#define B_    4
#define S_    2048
#define D_    1024
#define M_TOT (B_ * S_)          // 8192 rows of X (batch*seq flattened)

// Block tiling
#define BM 128
#define BN 128
#define BK 16
#define TM 8
#define TN 8
#define NTHREADS 256
#define SPAD 8                   // smem padding (floats), keeps float4 alignment

// Scratch (device globals: allocation-free per harness rules)
__device__ float g_Q[M_TOT * D_];            // 32 MB
__device__ float g_K[M_TOT * D_];            // 32 MB
__device__ float g_V[M_TOT * D_];            // 32 MB
__device__ float g_P[B_ * S_ * S_];          // 64 MB  (scores -> probs in place)

// ---------------------------------------------------------------------------
// Shared GEMM microkernel pieces
// ---------------------------------------------------------------------------

// Load a [128 x 16] tile whose source is K-major (row stride = ld, K contiguous),
// storing TRANSPOSED into smem tile T[BK][BM+SPAD] so compute reads are row-broadcast.
__device__ __forceinline__
void load_tile_kmajor_transposed(const float* __restrict__ src, int row0, int ld, int k0,
                                 float (*T)[BM + SPAD], int tid)
{
#pragma unroll
    for (int i = 0; i < 2; ++i) {
        int idx  = tid + i * NTHREADS;      // 0..511, each covers one float4
        int row  = idx >> 2;                // 0..127
        int kc4  = (idx & 3) * 4;           // 0,4,8,12
        float4 v = *(const float4*)&src[(row0 + row) * ld + k0 + kc4];
        T[kc4 + 0][row] = v.x;
        T[kc4 + 1][row] = v.y;
        T[kc4 + 2][row] = v.z;
        T[kc4 + 3][row] = v.w;
    }
}

// Load a [16 x 128] tile whose source is N-major (row stride = ld, N contiguous),
// storing directly into smem tile T[BK][BN+SPAD].
__device__ __forceinline__
void load_tile_nmajor_direct(const float* __restrict__ src, int k0, int ld, int n0,
                             float (*T)[BN + SPAD], int tid)
{
#pragma unroll
    for (int i = 0; i < 2; ++i) {
        int idx  = tid + i * NTHREADS;      // 0..511
        int row  = idx >> 5;                // k row 0..15
        int col  = (idx & 31) * 4;          // 0..124 step 4
        float4 v = *(const float4*)&src[(k0 + row) * ld + n0 + col];
        *(float4*)&T[row][col] = v;
    }
}

__device__ __forceinline__
void mma_step(const float (*As)[BM + SPAD], const float (*Bs)[BN + SPAD],
              int tm, int tn, float acc[TM][TN])
{
#pragma unroll
    for (int kk = 0; kk < BK; ++kk) {
        float a[TM], b[TN];
#pragma unroll
        for (int i = 0; i < TM; ++i) a[i] = As[kk][tm + i];
#pragma unroll
        for (int j = 0; j < TN; ++j) b[j] = Bs[kk][tn + j];
#pragma unroll
        for (int i = 0; i < TM; ++i)
#pragma unroll
            for (int j = 0; j < TN; ++j)
                acc[i][j] = fmaf(a[i], b[j], acc[i][j]);
    }
}

__device__ __forceinline__
void epilogue_store(float* __restrict__ C, int ldc, int m0, int n0,
                    int tm, int tn, const float acc[TM][TN], float alpha)
{
#pragma unroll
    for (int i = 0; i < TM; ++i) {
        float* dst = &C[(m0 + tm + i) * ldc + n0 + tn];
        float4 v0 = make_float4(alpha * acc[i][0], alpha * acc[i][1],
                                alpha * acc[i][2], alpha * acc[i][3]);
        float4 v1 = make_float4(alpha * acc[i][4], alpha * acc[i][5],
                                alpha * acc[i][6], alpha * acc[i][7]);
        *(float4*)&dst[0] = v0;
        *(float4*)&dst[4] = v1;
    }
}

// ---------------------------------------------------------------------------
// Kernel 1: fused QKV projection. C = X @ W^T  (NT GEMM), z selects W / output.
// M = 8192, N = 1024, K = 1024.
// ---------------------------------------------------------------------------
__global__ __launch_bounds__(NTHREADS, 2)
void gemm_qkv(const float* __restrict__ X,
              const float* __restrict__ Wq,
              const float* __restrict__ Wk,
              const float* __restrict__ Wv)
{
    __shared__ float As[BK][BM + SPAD];
    __shared__ float Bs[BK][BN + SPAD];

    const float* W = (blockIdx.z == 0) ? Wq : (blockIdx.z == 1) ? Wk : Wv;
    float*       C = (blockIdx.z == 0) ? g_Q : (blockIdx.z == 1) ? g_K : g_V;

    const int m0 = blockIdx.x * BM;
    const int n0 = blockIdx.y * BN;
    const int tid = threadIdx.x;
    const int tm = (tid / 16) * TM;
    const int tn = (tid % 16) * TN;

    float acc[TM][TN] = {};

    for (int k0 = 0; k0 < D_; k0 += BK) {
        load_tile_kmajor_transposed(X, m0, D_, k0, As, tid);
        load_tile_kmajor_transposed(W, n0, D_, k0, Bs, tid);
        __syncthreads();
        mma_step(As, Bs, tm, tn, acc);
        __syncthreads();
    }
    epilogue_store(C, D_, m0, n0, tm, tn, acc, 1.0f);
}

// ---------------------------------------------------------------------------
// Kernel 2: scores tile.  P[b,q,k] = (Q[b,q,:] . K[b,k,:]) / sqrt(D)
// NT GEMM per batch, only lower-triangular tiles (kt <= qt).
// ---------------------------------------------------------------------------
__global__ __launch_bounds__(NTHREADS, 2)
void gemm_scores()
{
    const int kt = blockIdx.x;
    const int qt = blockIdx.y;
    if (kt > qt) return;                   // strictly above diagonal: never read

    __shared__ float As[BK][BM + SPAD];
    __shared__ float Bs[BK][BN + SPAD];

    const int b = blockIdx.z;
    const float* Qb = g_Q + b * (S_ * D_);
    const float* Kb = g_K + b * (S_ * D_);
    float*       Cb = g_P + b * (S_ * S_);

    const int m0 = qt * BM;
    const int n0 = kt * BN;
    const int tid = threadIdx.x;
    const int tm = (tid / 16) * TM;
    const int tn = (tid % 16) * TN;

    float acc[TM][TN] = {};

    for (int k0 = 0; k0 < D_; k0 += BK) {
        load_tile_kmajor_transposed(Qb, m0, D_, k0, As, tid);
        load_tile_kmajor_transposed(Kb, n0, D_, k0, Bs, tid);
        __syncthreads();
        mma_step(As, Bs, tm, tn, acc);
        __syncthreads();
    }
    epilogue_store(Cb, S_, m0, n0, tm, tn, acc, 0.03125f);   // 1/sqrt(1024)
}

// ---------------------------------------------------------------------------
// Kernel 3: causal row softmax, in place on g_P.
// One block per (q, b) row. Each thread keeps its 8 strided elements in
// registers (2048 = 256*8 exactly). Masked tail (k > q) written as 0 so the
// PV GEMM can consume full 128-wide tiles up to the diagonal.
// ---------------------------------------------------------------------------
__global__ __launch_bounds__(NTHREADS)
void softmax_causal()
{
    const int q = blockIdx.x;
    const int b = blockIdx.y;
    float* row = g_P + (size_t)(b * S_ + q) * S_;
    const int len = q + 1;

    const int tid  = threadIdx.x;
    const int lane = tid & 31;
    const int wid  = tid >> 5;

    float v[8];
    float m = -3.0e38f;
#pragma unroll
    for (int j = 0; j < 8; ++j) {
        int idx = tid + j * NTHREADS;
        v[j] = (idx < len) ? row[idx] : -3.0e38f;
        m = fmaxf(m, v[j]);
    }
#pragma unroll
    for (int off = 16; off > 0; off >>= 1)
        m = fmaxf(m, __shfl_xor_sync(0xFFFFFFFFu, m, off));

    __shared__ float red[8];
    __shared__ float s_max, s_sum;
    if (lane == 0) red[wid] = m;
    __syncthreads();
    if (tid == 0) {
        float mm = red[0];
#pragma unroll
        for (int i = 1; i < 8; ++i) mm = fmaxf(mm, red[i]);
        s_max = mm;
    }
    __syncthreads();
    const float rmax = s_max;

    float s = 0.0f;
#pragma unroll
    for (int j = 0; j < 8; ++j) {
        int idx = tid + j * NTHREADS;
        float e = (idx < len) ? __expf(v[j] - rmax) : 0.0f;
        v[j] = e;
        s += e;
    }
#pragma unroll
    for (int off = 16; off > 0; off >>= 1)
        s += __shfl_xor_sync(0xFFFFFFFFu, s, off);
    if (lane == 0) red[wid] = s;
    __syncthreads();
    if (tid == 0) {
        float ss = 0.0f;
#pragma unroll
        for (int i = 0; i < 8; ++i) ss += red[i];
        s_sum = ss;
    }
    __syncthreads();
    const float inv = 1.0f / s_sum;

#pragma unroll
    for (int j = 0; j < 8; ++j) {
        int idx = tid + j * NTHREADS;
        row[idx] = v[j] * inv;             // masked entries are 0 * inv = 0
    }
}

// ---------------------------------------------------------------------------
// Kernel 4: Out[b,q,d] = sum_k P[b,q,k] * V[b,k,d]   (NN GEMM per batch)
// Internal k-tile loop runs only up to the diagonal tile of the q-tile.
// ---------------------------------------------------------------------------
__global__ __launch_bounds__(NTHREADS, 2)
void gemm_pv(float* __restrict__ Out)
{
    const int nt = blockIdx.x;
    const int qt = blockIdx.y;
    const int b  = blockIdx.z;

    __shared__ float As[BK][BM + SPAD];
    __shared__ float Bs[BK][BN + SPAD];

    const float* Pb = g_P + b * (S_ * S_);
    const float* Vb = g_V + b * (S_ * D_);
    float*       Cb = Out + b * (S_ * D_);

    const int m0 = qt * BM;
    const int n0 = nt * BN;
    const int tid = threadIdx.x;
    const int tm = (tid / 16) * TM;
    const int tn = (tid % 16) * TN;

    float acc[TM][TN] = {};

    const int kend = (qt + 1) * BM;        // causal: k tiles up to and incl. diagonal
    for (int k0 = 0; k0 < kend; k0 += BK) {
        load_tile_kmajor_transposed(Pb, m0, S_, k0, As, tid);  // P is k-contiguous
        load_tile_nmajor_direct(Vb, k0, D_, n0, Bs, tid);       // V is d-contiguous
        __syncthreads();
        mma_step(As, Bs, tm, tn, acc);
        __syncthreads();
    }
    epilogue_store(Cb, D_, m0, n0, tm, tn, acc, 1.0f);
}

// ---------------------------------------------------------------------------
// Launch
// ---------------------------------------------------------------------------
extern "C" void kernel_launch(void* const* d_in, const int* in_sizes, int n_in,
                              void* d_out, int out_size)
{
    const float* X  = (const float*)d_in[0];
    const float* Wq = (const float*)d_in[1];
    const float* Wk = (const float*)d_in[2];
    const float* Wv = (const float*)d_in[3];
    float* Out = (float*)d_out;

    dim3 blk(NTHREADS);

    // 1) Q,K,V projections
    gemm_qkv<<<dim3(M_TOT / BM, D_ / BN, 3), blk>>>(X, Wq, Wk, Wv);

    // 2) causal scores (lower-triangular tiles only; others exit immediately)
    gemm_scores<<<dim3(S_ / BN, S_ / BM, B_), blk>>>();

    // 3) row softmax with masked-tail zeroing
    softmax_causal<<<dim3(S_, B_), blk>>>();

    // 4) attention-weighted V
    gemm_pv<<<dim3(D_ / BN, S_ / BM, B_), blk>>>(Out);
}

// round 3
// speedup vs baseline: 3.5029x; 3.5029x over previous
#include <cuda_runtime.h>
#include <cstdint>

// Problem constants
#define B_    4
#define S_    2048
#define D_    1024
#define M_TOT (B_ * S_)

// Block tiling for tf32 mma kernels
#define BM 128
#define BN 128
#define BKK 32                    // k per block iter (4 mma k-steps of 8)
#define NTHREADS 256              // 8 warps: warp_m in 0..3 (m32), warp_n in 0..1 (n64)
#define LDA 36                    // padded row (floats) for [row][k] smem tiles
#define LDNV 136                  // padded row for PV's V tile [k][n]

// Scratch
__device__ float g_Q[M_TOT * D_];
__device__ float g_K[M_TOT * D_];
__device__ float g_V[M_TOT * D_];
__device__ float g_P[B_ * S_ * S_];

// ---------------------------------------------------------------------------
// PTX helpers
// ---------------------------------------------------------------------------
__device__ __forceinline__ uint32_t smem_u32(const void* p) {
    return (uint32_t)__cvta_generic_to_shared(p);
}

__device__ __forceinline__ uint32_t f2tf32(float f) {
    uint32_t r;
    asm("cvt.rna.tf32.f32 %0, %1;" : "=r"(r) : "f"(f));
    return r;
}

__device__ __forceinline__ void ldsm_x4(uint32_t addr, uint32_t& r0, uint32_t& r1,
                                        uint32_t& r2, uint32_t& r3) {
    asm volatile("ldmatrix.sync.aligned.m8n8.x4.shared.b16 {%0,%1,%2,%3}, [%4];"
                 : "=r"(r0), "=r"(r1), "=r"(r2), "=r"(r3) : "r"(addr));
}

__device__ __forceinline__ void mma_tf32(float* c, uint32_t a0, uint32_t a1,
                                         uint32_t a2, uint32_t a3,
                                         uint32_t b0, uint32_t b1) {
    asm volatile(
        "mma.sync.aligned.m16n8k8.row.col.f32.tf32.tf32.f32 "
        "{%0,%1,%2,%3}, {%4,%5,%6,%7}, {%8,%9}, {%0,%1,%2,%3};"
        : "+f"(c[0]), "+f"(c[1]), "+f"(c[2]), "+f"(c[3])
        : "r"(a0), "r"(a1), "r"(a2), "r"(a3), "r"(b0), "r"(b1));
}

// ---------------------------------------------------------------------------
// gmem -> smem tile copy, k-contiguous source, tf32 convert.
// Dest tile: [128 rows][BKK k] at row stride LDA. Each quarter-warp covers one
// row (8 float4 segments) -> conflict-free STS.128.
// ---------------------------------------------------------------------------
__device__ __forceinline__
void copy_tile_kc(const float* __restrict__ src, int row0, int ld, int k0,
                  uint32_t* __restrict__ dst, int tid)
{
#pragma unroll
    for (int i = 0; i < 4; ++i) {
        int idx = tid + i * NTHREADS;        // 0..1023
        int r   = idx >> 3;                  // 0..127
        int k4  = (idx & 7) << 2;            // 0,4,..,28
        float4 v = *(const float4*)&src[(size_t)(row0 + r) * ld + k0 + k4];
        uint32_t* d = dst + r * LDA + k4;
        d[0] = f2tf32(v.x); d[1] = f2tf32(v.y);
        d[2] = f2tf32(v.z); d[3] = f2tf32(v.w);
    }
}

// V tile copy for PV: source [k][n] n-contiguous -> dst [BKK][LDNV].
__device__ __forceinline__
void copy_tile_nc(const float* __restrict__ src, int k0, int ld, int n0,
                  uint32_t* __restrict__ dst, int tid)
{
#pragma unroll
    for (int i = 0; i < 4; ++i) {
        int idx = tid + i * NTHREADS;        // 0..1023
        int r   = idx >> 5;                  // k row 0..31
        int n4  = (idx & 31) << 2;           // 0..124
        float4 v = *(const float4*)&src[(size_t)(k0 + r) * ld + n0 + n4];
        uint32_t* d = dst + r * LDNV + n4;
        d[0] = f2tf32(v.x); d[1] = f2tf32(v.y);
        d[2] = f2tf32(v.z); d[3] = f2tf32(v.w);
    }
}

// ---------------------------------------------------------------------------
// Warp-tile compute: A via ldmatrix from As[128][LDA], B via ldmatrix from
// Bs[128][LDA] ([n][k] layout). acc[2][8][4].
// ---------------------------------------------------------------------------
__device__ __forceinline__
void warp_mma_ldsmB(const uint32_t* As, const uint32_t* Bs,
                    int warp_m, int warp_n, int lane, float acc[2][8][4])
{
    const int aRow  = warp_m * 32 + (lane & 15);
    const int aKoff = (lane >> 4) * 4;
    const int bRow  = warp_n * 64 + ((lane >> 4) << 3) + (lane & 7);
    const int bKoff = ((lane >> 3) & 1) * 4;

#pragma unroll
    for (int ks = 0; ks < 4; ++ks) {
        uint32_t a[2][4];
#pragma unroll
        for (int mt = 0; mt < 2; ++mt) {
            uint32_t addr = smem_u32(As + (aRow + mt * 16) * LDA + ks * 8 + aKoff);
            ldsm_x4(addr, a[mt][0], a[mt][1], a[mt][2], a[mt][3]);
        }
        uint32_t b[8][2];
#pragma unroll
        for (int np = 0; np < 4; ++np) {
            uint32_t addr = smem_u32(Bs + (bRow + np * 16) * LDA + ks * 8 + bKoff);
            ldsm_x4(addr, b[2 * np][0], b[2 * np][1], b[2 * np + 1][0], b[2 * np + 1][1]);
        }
#pragma unroll
        for (int mt = 0; mt < 2; ++mt)
#pragma unroll
            for (int nt = 0; nt < 8; ++nt)
                mma_tf32(acc[mt][nt], a[mt][0], a[mt][1], a[mt][2], a[mt][3],
                         b[nt][0], b[nt][1]);
    }
}

// Warp-tile compute for PV: B via direct LDS.32 from Bs[BKK][LDNV].
__device__ __forceinline__
void warp_mma_ldsB(const uint32_t* As, const uint32_t* Bs,
                   int warp_m, int warp_n, int lane, float acc[2][8][4])
{
    const int aRow  = warp_m * 32 + (lane & 15);
    const int aKoff = (lane >> 4) * 4;
    const int bCol  = warp_n * 64 + (lane >> 2);   // n base for this thread
    const int bK    = lane & 3;                    // k within k-step

#pragma unroll
    for (int ks = 0; ks < 4; ++ks) {
        uint32_t a[2][4];
#pragma unroll
        for (int mt = 0; mt < 2; ++mt) {
            uint32_t addr = smem_u32(As + (aRow + mt * 16) * LDA + ks * 8 + aKoff);
            ldsm_x4(addr, a[mt][0], a[mt][1], a[mt][2], a[mt][3]);
        }
        const uint32_t* b0p = Bs + (ks * 8 + bK) * LDNV + bCol;
        const uint32_t* b1p = b0p + 4 * LDNV;
        uint32_t b[8][2];
#pragma unroll
        for (int nt = 0; nt < 8; ++nt) {
            b[nt][0] = b0p[nt * 8];
            b[nt][1] = b1p[nt * 8];
        }
#pragma unroll
        for (int mt = 0; mt < 2; ++mt)
#pragma unroll
            for (int nt = 0; nt < 8; ++nt)
                mma_tf32(acc[mt][nt], a[mt][0], a[mt][1], a[mt][2], a[mt][3],
                         b[nt][0], b[nt][1]);
    }
}

__device__ __forceinline__
void epilogue_mma(float* __restrict__ C, int ldc, int m0, int n0,
                  int warp_m, int warp_n, int lane,
                  const float acc[2][8][4], float alpha)
{
    const int g = lane >> 2;
    const int c2 = (lane & 3) * 2;
#pragma unroll
    for (int mt = 0; mt < 2; ++mt) {
        int row = m0 + warp_m * 32 + mt * 16 + g;
#pragma unroll
        for (int nt = 0; nt < 8; ++nt) {
            int col = n0 + warp_n * 64 + nt * 8 + c2;
            float2 v0 = make_float2(alpha * acc[mt][nt][0], alpha * acc[mt][nt][1]);
            float2 v1 = make_float2(alpha * acc[mt][nt][2], alpha * acc[mt][nt][3]);
            *(float2*)&C[(size_t)row * ldc + col] = v0;
            *(float2*)&C[(size_t)(row + 8) * ldc + col] = v1;
        }
    }
}

// ---------------------------------------------------------------------------
// Kernel 1: QKV projection. C = X @ W^T, z selects weight/output.
// ---------------------------------------------------------------------------
__global__ __launch_bounds__(NTHREADS)
void gemm_qkv(const float* __restrict__ X,
              const float* __restrict__ Wq,
              const float* __restrict__ Wk,
              const float* __restrict__ Wv)
{
    __shared__ uint32_t As[BM * LDA];
    __shared__ uint32_t Bs[BN * LDA];

    const float* W = (blockIdx.z == 0) ? Wq : (blockIdx.z == 1) ? Wk : Wv;
    float*       C = (blockIdx.z == 0) ? g_Q : (blockIdx.z == 1) ? g_K : g_V;

    const int m0 = blockIdx.x * BM;
    const int n0 = blockIdx.y * BN;
    const int tid = threadIdx.x;
    const int lane = tid & 31;
    const int w = tid >> 5;
    const int warp_m = w & 3, warp_n = w >> 2;

    float acc[2][8][4] = {};

    for (int k0 = 0; k0 < D_; k0 += BKK) {
        copy_tile_kc(X, m0, D_, k0, As, tid);
        copy_tile_kc(W, n0, D_, k0, Bs, tid);
        __syncthreads();
        warp_mma_ldsmB(As, Bs, warp_m, warp_n, lane, acc);
        __syncthreads();
    }
    epilogue_mma(C, D_, m0, n0, warp_m, warp_n, lane, acc, 1.0f);
}

// ---------------------------------------------------------------------------
// Kernel 2: scores = (Q K^T)/sqrt(D), lower-triangular tiles only.
// ---------------------------------------------------------------------------
__global__ __launch_bounds__(NTHREADS)
void gemm_scores()
{
    const int kt = blockIdx.x;
    const int qt = blockIdx.y;
    if (kt > qt) return;

    __shared__ uint32_t As[BM * LDA];
    __shared__ uint32_t Bs[BN * LDA];

    const int b = blockIdx.z;
    const float* Qb = g_Q + (size_t)b * (S_ * D_);
    const float* Kb = g_K + (size_t)b * (S_ * D_);
    float*       Cb = g_P + (size_t)b * (S_ * S_);

    const int m0 = qt * BM;
    const int n0 = kt * BN;
    const int tid = threadIdx.x;
    const int lane = tid & 31;
    const int w = tid >> 5;
    const int warp_m = w & 3, warp_n = w >> 2;

    float acc[2][8][4] = {};

    for (int k0 = 0; k0 < D_; k0 += BKK) {
        copy_tile_kc(Qb, m0, D_, k0, As, tid);
        copy_tile_kc(Kb, n0, D_, k0, Bs, tid);
        __syncthreads();
        warp_mma_ldsmB(As, Bs, warp_m, warp_n, lane, acc);
        __syncthreads();
    }
    epilogue_mma(Cb, S_, m0, n0, warp_m, warp_n, lane, acc, 0.03125f);
}

// ---------------------------------------------------------------------------
// Kernel 3: causal row softmax (unchanged, writes full row incl. zeroed tail).
// ---------------------------------------------------------------------------
__global__ __launch_bounds__(NTHREADS)
void softmax_causal()
{
    const int q = blockIdx.x;
    const int b = blockIdx.y;
    float* row = g_P + (size_t)(b * S_ + q) * S_;
    const int len = q + 1;

    const int tid  = threadIdx.x;
    const int lane = tid & 31;
    const int wid  = tid >> 5;

    float v[8];
    float m = -3.0e38f;
#pragma unroll
    for (int j = 0; j < 8; ++j) {
        int idx = tid + j * NTHREADS;
        v[j] = (idx < len) ? row[idx] : -3.0e38f;
        m = fmaxf(m, v[j]);
    }
#pragma unroll
    for (int off = 16; off > 0; off >>= 1)
        m = fmaxf(m, __shfl_xor_sync(0xFFFFFFFFu, m, off));

    __shared__ float red[8];
    __shared__ float s_max, s_sum;
    if (lane == 0) red[wid] = m;
    __syncthreads();
    if (tid == 0) {
        float mm = red[0];
#pragma unroll
        for (int i = 1; i < 8; ++i) mm = fmaxf(mm, red[i]);
        s_max = mm;
    }
    __syncthreads();
    const float rmax = s_max;

    float s = 0.0f;
#pragma unroll
    for (int j = 0; j < 8; ++j) {
        int idx = tid + j * NTHREADS;
        float e = (idx < len) ? __expf(v[j] - rmax) : 0.0f;
        v[j] = e;
        s += e;
    }
#pragma unroll
    for (int off = 16; off > 0; off >>= 1)
        s += __shfl_xor_sync(0xFFFFFFFFu, s, off);
    if (lane == 0) red[wid] = s;
    __syncthreads();
    if (tid == 0) {
        float ss = 0.0f;
#pragma unroll
        for (int i = 0; i < 8; ++i) ss += red[i];
        s_sum = ss;
    }
    __syncthreads();
    const float inv = 1.0f / s_sum;

#pragma unroll
    for (int j = 0; j < 8; ++j) {
        int idx = tid + j * NTHREADS;
        row[idx] = v[j] * inv;
    }
}

// ---------------------------------------------------------------------------
// Kernel 4: Out = P @ V, k-loop up to the diagonal tile.
// ---------------------------------------------------------------------------
__global__ __launch_bounds__(NTHREADS)
void gemm_pv(float* __restrict__ Out)
{
    __shared__ uint32_t As[BM * LDA];
    __shared__ uint32_t Bs[BKK * LDNV];

    const int nt = blockIdx.x;
    const int qt = blockIdx.y;
    const int b  = blockIdx.z;

    const float* Pb = g_P + (size_t)b * (S_ * S_);
    const float* Vb = g_V + (size_t)b * (S_ * D_);
    float*       Cb = Out + (size_t)b * (S_ * D_);

    const int m0 = qt * BM;
    const int n0 = nt * BN;
    const int tid = threadIdx.x;
    const int lane = tid & 31;
    const int w = tid >> 5;
    const int warp_m = w & 3, warp_n = w >> 2;

    float acc[2][8][4] = {};

    const int kend = (qt + 1) * BM;
    for (int k0 = 0; k0 < kend; k0 += BKK) {
        copy_tile_kc(Pb, m0, S_, k0, As, tid);   // P: k-contiguous
        copy_tile_nc(Vb, k0, D_, n0, Bs, tid);   // V: n-contiguous
        __syncthreads();
        warp_mma_ldsB(As, Bs, warp_m, warp_n, lane, acc);
        __syncthreads();
    }
    epilogue_mma(Cb, D_, m0, n0, warp_m, warp_n, lane, acc, 1.0f);
}

// ---------------------------------------------------------------------------
// Launch
// ---------------------------------------------------------------------------
extern "C" void kernel_launch(void* const* d_in, const int* in_sizes, int n_in,
                              void* d_out, int out_size)
{
    const float* X  = (const float*)d_in[0];
    const float* Wq = (const float*)d_in[1];
    const float* Wk = (const float*)d_in[2];
    const float* Wv = (const float*)d_in[3];
    float* Out = (float*)d_out;

    dim3 blk(NTHREADS);

    gemm_qkv<<<dim3(M_TOT / BM, D_ / BN, 3), blk>>>(X, Wq, Wk, Wv);
    gemm_scores<<<dim3(S_ / BN, S_ / BM, B_), blk>>>();
    softmax_causal<<<dim3(S_, B_), blk>>>();
    gemm_pv<<<dim3(D_ / BN, S_ / BM, B_), blk>>>(Out);
}

// round 4
// speedup vs baseline: 4.3908x; 1.2534x over previous
#include <cuda_runtime.h>
#include <cstdint>

// Problem constants
#define B_    4
#define S_    2048
#define D_    1024
#define M_TOT (B_ * S_)

// Tiling
#define BM 128
#define BN 128
#define BKK 32                    // k per mainloop iter (4 mma k-steps of 8)
#define NTHREADS 256              // 8 warps: 4 (m32) x 2 (n64)
#define STAGES 3
#define STAGE_FLOATS 8192         // A(128x32) + B(128x32)
#define SMEM_BYTES (STAGES * STAGE_FLOATS * 4)   // 98304

// Scratch (tf32-prerounded operands live here)
__device__ float g_X [M_TOT * D_];           // rounded X
__device__ float g_W [3 * D_ * D_];          // rounded Wq|Wk|Wv
__device__ float g_Q [M_TOT * D_];           // rounded Q
__device__ float g_K [M_TOT * D_];           // rounded K
__device__ float g_Vt[M_TOT * D_];           // rounded V, transposed [b][d][s]
__device__ float g_P [B_ * S_ * S_];         // scores -> rounded probs

// ---------------------------------------------------------------------------
// PTX helpers
// ---------------------------------------------------------------------------
__device__ __forceinline__ uint32_t smem_u32(const void* p) {
    return (uint32_t)__cvta_generic_to_shared(p);
}
__device__ __forceinline__ uint32_t f2tf32(float f) {
    uint32_t r;
    asm("cvt.rna.tf32.f32 %0, %1;" : "=r"(r) : "f"(f));
    return r;
}
__device__ __forceinline__ float roundtf(float f) { return __uint_as_float(f2tf32(f)); }

__device__ __forceinline__ void ldsm_x4(uint32_t addr, uint32_t& r0, uint32_t& r1,
                                        uint32_t& r2, uint32_t& r3) {
    asm volatile("ldmatrix.sync.aligned.m8n8.x4.shared.b16 {%0,%1,%2,%3}, [%4];"
                 : "=r"(r0), "=r"(r1), "=r"(r2), "=r"(r3) : "r"(addr));
}
__device__ __forceinline__ void mma_tf32(float* c, uint32_t a0, uint32_t a1,
                                         uint32_t a2, uint32_t a3,
                                         uint32_t b0, uint32_t b1) {
    asm volatile(
        "mma.sync.aligned.m16n8k8.row.col.f32.tf32.tf32.f32 "
        "{%0,%1,%2,%3}, {%4,%5,%6,%7}, {%8,%9}, {%0,%1,%2,%3};"
        : "+f"(c[0]), "+f"(c[1]), "+f"(c[2]), "+f"(c[3])
        : "r"(a0), "r"(a1), "r"(a2), "r"(a3), "r"(b0), "r"(b1));
}
__device__ __forceinline__ void cp16(uint32_t saddr, const float* g) {
    asm volatile("cp.async.cg.shared.global [%0], [%1], 16;" :: "r"(saddr), "l"(g));
}
__device__ __forceinline__ void cp_commit() { asm volatile("cp.async.commit_group;"); }
__device__ __forceinline__ void cp_wait1()  { asm volatile("cp.async.wait_group 1;"); }

// XOR-swizzled float offset within a [128][32] tile (16B chunk granularity).
__device__ __forceinline__ int swz(int r, int c) {
    return (r << 5) + (((c ^ (r & 7)) & 7) << 2);
}

// ---------------------------------------------------------------------------
// cp.async one stage: A tile [128][32] from gA (k-contig, ld ldA), B likewise.
// ---------------------------------------------------------------------------
__device__ __forceinline__
void issue_stage(const float* __restrict__ gA, const float* __restrict__ gB,
                 int ldA, int ldB, float* stage, int tid)
{
#pragma unroll
    for (int i = 0; i < 4; ++i) {
        int idx = tid + i * NTHREADS;       // 0..1023
        int r = idx >> 3, c = idx & 7;
        cp16(smem_u32(stage + swz(r, c)), gA + (size_t)r * ldA + c * 4);
    }
#pragma unroll
    for (int i = 0; i < 4; ++i) {
        int idx = tid + i * NTHREADS;
        int r = idx >> 3, c = idx & 7;
        cp16(smem_u32(stage + 4096 + swz(r, c)), gB + (size_t)r * ldB + c * 4);
    }
}

// ---------------------------------------------------------------------------
// Warp compute over one stage (4 mma k-steps).
// ---------------------------------------------------------------------------
__device__ __forceinline__
void warp_compute(const float* stage, int warp_m, int warp_n, int lane,
                  float acc[2][8][4])
{
    const float* As = stage;
    const float* Bs = stage + 4096;
    const int aR = warp_m * 32 + (lane & 15);
    const int aC = (lane >> 4);                           // 0/1
    const int bR = warp_n * 64 + ((lane >> 4) << 3) + (lane & 7);
    const int bC = ((lane >> 3) & 1);

#pragma unroll
    for (int ks = 0; ks < 4; ++ks) {
        uint32_t a[2][4];
#pragma unroll
        for (int mt = 0; mt < 2; ++mt) {
            uint32_t addr = smem_u32(As + swz(aR + mt * 16, ks * 2 + aC));
            ldsm_x4(addr, a[mt][0], a[mt][1], a[mt][2], a[mt][3]);
        }
        uint32_t b[8][2];
#pragma unroll
        for (int np = 0; np < 4; ++np) {
            uint32_t addr = smem_u32(Bs + swz(bR + np * 16, ks * 2 + bC));
            ldsm_x4(addr, b[2 * np][0], b[2 * np][1], b[2 * np + 1][0], b[2 * np + 1][1]);
        }
#pragma unroll
        for (int mt = 0; mt < 2; ++mt)
#pragma unroll
            for (int nt = 0; nt < 8; ++nt)
                mma_tf32(acc[mt][nt], a[mt][0], a[mt][1], a[mt][2], a[mt][3],
                         b[nt][0], b[nt][1]);
    }
}

// ---------------------------------------------------------------------------
// Pipelined mainloop: 3-stage cp.async, one sync per iter.
// ---------------------------------------------------------------------------
__device__ __forceinline__
void gemm_mainloop(const float* __restrict__ gA, const float* __restrict__ gB,
                   int ldA, int ldB, int niter, float* smem, int tid,
                   int warp_m, int warp_n, int lane, float acc[2][8][4])
{
    issue_stage(gA,      gB,      ldA, ldB, smem,                tid); cp_commit();
    issue_stage(gA + 32, gB + 32, ldA, ldB, smem + STAGE_FLOATS, tid); cp_commit();

    for (int i = 0; i < niter; ++i) {
        cp_wait1();
        __syncthreads();
        if (i + 2 < niter)
            issue_stage(gA + (size_t)(i + 2) * BKK, gB + (size_t)(i + 2) * BKK,
                        ldA, ldB, smem + ((i + 2) % STAGES) * STAGE_FLOATS, tid);
        cp_commit();
        warp_compute(smem + (i % STAGES) * STAGE_FLOATS, warp_m, warp_n, lane, acc);
    }
}

__device__ __forceinline__
void epilogue_plain(float* __restrict__ C, int ldc, int m0, int n0,
                    int warp_m, int warp_n, int lane,
                    const float acc[2][8][4], float alpha, bool roundOut)
{
    const int g = lane >> 2;
    const int c2 = (lane & 3) * 2;
#pragma unroll
    for (int mt = 0; mt < 2; ++mt) {
        int row = m0 + warp_m * 32 + mt * 16 + g;
#pragma unroll
        for (int nt = 0; nt < 8; ++nt) {
            int col = n0 + warp_n * 64 + nt * 8 + c2;
            float x0 = alpha * acc[mt][nt][0], x1 = alpha * acc[mt][nt][1];
            float x2 = alpha * acc[mt][nt][2], x3 = alpha * acc[mt][nt][3];
            if (roundOut) { x0 = roundtf(x0); x1 = roundtf(x1); x2 = roundtf(x2); x3 = roundtf(x3); }
            *(float2*)&C[(size_t)row * ldc + col]       = make_float2(x0, x1);
            *(float2*)&C[(size_t)(row + 8) * ldc + col] = make_float2(x2, x3);
        }
    }
}

// ---------------------------------------------------------------------------
// Kernel 0: tf32 pre-round copy.
// ---------------------------------------------------------------------------
__global__ __launch_bounds__(NTHREADS)
void round_copy(const float* __restrict__ src, float* __restrict__ dst, int n4)
{
    int i = blockIdx.x * NTHREADS + threadIdx.x;
    if (i < n4) {
        float4 v = ((const float4*)src)[i];
        v.x = roundtf(v.x); v.y = roundtf(v.y);
        v.z = roundtf(v.z); v.w = roundtf(v.w);
        ((float4*)dst)[i] = v;
    }
}

// ---------------------------------------------------------------------------
// Kernel 1: QKV projection (z selects W / output). Q,K stored rounded;
// V stored rounded AND transposed into g_Vt[b][d][s].
// ---------------------------------------------------------------------------
__global__ __launch_bounds__(NTHREADS, 2)
void gemm_qkv()
{
    extern __shared__ float smem[];
    const int z = blockIdx.z;
    const float* A = g_X;
    const float* Bm = g_W + (size_t)z * D_ * D_;

    const int m0 = blockIdx.x * BM;
    const int n0 = blockIdx.y * BN;
    const int tid = threadIdx.x;
    const int lane = tid & 31;
    const int w = tid >> 5;
    const int warp_m = w & 3, warp_n = w >> 2;

    float acc[2][8][4] = {};
    gemm_mainloop(A + (size_t)m0 * D_, Bm + (size_t)n0 * D_, D_, D_,
                  D_ / BKK, smem, tid, warp_m, warp_n, lane, acc);

    if (z < 2) {
        float* C = (z == 0) ? g_Q : g_K;
        epilogue_plain(C, D_, m0, n0, warp_m, warp_n, lane, acc, 1.0f, true);
    } else {
        // transposed store: g_Vt[(b*D + col)*S + s], m = b*S + s
        const int g = lane >> 2;
        const int c2 = (lane & 3) * 2;
#pragma unroll
        for (int mt = 0; mt < 2; ++mt) {
            int row = m0 + warp_m * 32 + mt * 16 + g;
            int b = row >> 11, s = row & (S_ - 1);
            int row8 = row + 8, s8 = s + 8;   // same b (m0 tiles never straddle batches)
#pragma unroll
            for (int nt = 0; nt < 8; ++nt) {
                int col = n0 + warp_n * 64 + nt * 8 + c2;
                size_t base0 = ((size_t)(b * D_ + col)) * S_;
                size_t base1 = ((size_t)(b * D_ + col + 1)) * S_;
                g_Vt[base0 + s]  = roundtf(acc[mt][nt][0]);
                g_Vt[base1 + s]  = roundtf(acc[mt][nt][1]);
                g_Vt[base0 + s8] = roundtf(acc[mt][nt][2]);
                g_Vt[base1 + s8] = roundtf(acc[mt][nt][3]);
            }
        }
    }
}

// ---------------------------------------------------------------------------
// Kernel 2: scores = (Q K^T)/sqrt(D), lower-triangular tiles only.
// ---------------------------------------------------------------------------
__global__ __launch_bounds__(NTHREADS, 2)
void gemm_scores()
{
    const int kt = blockIdx.x;
    const int qt = blockIdx.y;
    if (kt > qt) return;
    extern __shared__ float smem[];

    const int b = blockIdx.z;
    const float* Qb = g_Q + (size_t)b * (S_ * D_);
    const float* Kb = g_K + (size_t)b * (S_ * D_);
    float*       Cb = g_P + (size_t)b * (S_ * S_);

    const int m0 = qt * BM;
    const int n0 = kt * BN;
    const int tid = threadIdx.x;
    const int lane = tid & 31;
    const int w = tid >> 5;
    const int warp_m = w & 3, warp_n = w >> 2;

    float acc[2][8][4] = {};
    gemm_mainloop(Qb + (size_t)m0 * D_, Kb + (size_t)n0 * D_, D_, D_,
                  D_ / BKK, smem, tid, warp_m, warp_n, lane, acc);
    epilogue_plain(Cb, S_, m0, n0, warp_m, warp_n, lane, acc, 0.03125f, false);
}

// ---------------------------------------------------------------------------
// Kernel 3: causal row softmax; stores tf32-rounded probs (zeros in tail).
// ---------------------------------------------------------------------------
__global__ __launch_bounds__(NTHREADS)
void softmax_causal()
{
    const int q = blockIdx.x;
    const int b = blockIdx.y;
    float* row = g_P + (size_t)(b * S_ + q) * S_;
    const int len = q + 1;

    const int tid  = threadIdx.x;
    const int lane = tid & 31;
    const int wid  = tid >> 5;

    float v[8];
    float m = -3.0e38f;
#pragma unroll
    for (int j = 0; j < 8; ++j) {
        int idx = tid + j * NTHREADS;
        v[j] = (idx < len) ? row[idx] : -3.0e38f;
        m = fmaxf(m, v[j]);
    }
#pragma unroll
    for (int off = 16; off > 0; off >>= 1)
        m = fmaxf(m, __shfl_xor_sync(0xFFFFFFFFu, m, off));

    __shared__ float red[8];
    __shared__ float s_max, s_sum;
    if (lane == 0) red[wid] = m;
    __syncthreads();
    if (tid == 0) {
        float mm = red[0];
#pragma unroll
        for (int i = 1; i < 8; ++i) mm = fmaxf(mm, red[i]);
        s_max = mm;
    }
    __syncthreads();
    const float rmax = s_max;

    float s = 0.0f;
#pragma unroll
    for (int j = 0; j < 8; ++j) {
        int idx = tid + j * NTHREADS;
        float e = (idx < len) ? __expf(v[j] - rmax) : 0.0f;
        v[j] = e;
        s += e;
    }
#pragma unroll
    for (int off = 16; off > 0; off >>= 1)
        s += __shfl_xor_sync(0xFFFFFFFFu, s, off);
    if (lane == 0) red[wid] = s;
    __syncthreads();
    if (tid == 0) {
        float ss = 0.0f;
#pragma unroll
        for (int i = 0; i < 8; ++i) ss += red[i];
        s_sum = ss;
    }
    __syncthreads();
    const float inv = 1.0f / s_sum;

#pragma unroll
    for (int j = 0; j < 8; ++j) {
        int idx = tid + j * NTHREADS;
        row[idx] = roundtf(v[j] * inv);
    }
}

// ---------------------------------------------------------------------------
// Kernel 4: Out = P @ Vt^T (NT form), k-loop up to the causal diagonal.
// ---------------------------------------------------------------------------
__global__ __launch_bounds__(NTHREADS, 2)
void gemm_pv(float* __restrict__ Out)
{
    extern __shared__ float smem[];
    const int nt = blockIdx.x;
    const int qt = blockIdx.y;
    const int b  = blockIdx.z;

    const float* Pb = g_P  + (size_t)b * (S_ * S_);
    const float* Vb = g_Vt + (size_t)b * (S_ * D_);   // [d][s]
    float*       Cb = Out  + (size_t)b * (S_ * D_);

    const int m0 = qt * BM;
    const int n0 = nt * BN;
    const int tid = threadIdx.x;
    const int lane = tid & 31;
    const int w = tid >> 5;
    const int warp_m = w & 3, warp_n = w >> 2;

    float acc[2][8][4] = {};
    const int niter = (qt + 1) * (BM / BKK);          // causal k extent
    gemm_mainloop(Pb + (size_t)m0 * S_, Vb + (size_t)n0 * S_, S_, S_,
                  niter, smem, tid, warp_m, warp_n, lane, acc);
    epilogue_plain(Cb, D_, m0, n0, warp_m, warp_n, lane, acc, 1.0f, false);
}

// ---------------------------------------------------------------------------
// Launch
// ---------------------------------------------------------------------------
extern "C" void kernel_launch(void* const* d_in, const int* in_sizes, int n_in,
                              void* d_out, int out_size)
{
    const float* X  = (const float*)d_in[0];
    const float* Wq = (const float*)d_in[1];
    const float* Wk = (const float*)d_in[2];
    const float* Wv = (const float*)d_in[3];
    float* Out = (float*)d_out;

    // Opt-in to 96KB dynamic smem (idempotent; not a stream op).
    cudaFuncSetAttribute(gemm_qkv,    cudaFuncAttributeMaxDynamicSharedMemorySize, SMEM_BYTES);
    cudaFuncSetAttribute(gemm_scores, cudaFuncAttributeMaxDynamicSharedMemorySize, SMEM_BYTES);
    cudaFuncSetAttribute(gemm_pv,     cudaFuncAttributeMaxDynamicSharedMemorySize, SMEM_BYTES);

    dim3 blk(NTHREADS);

    // 0) pre-round inputs to tf32
    float* gX; cudaGetSymbolAddress((void**)&gX, g_X);
    float* gW; cudaGetSymbolAddress((void**)&gW, g_W);
    const int nX4 = (M_TOT * D_) / 4;
    const int nW4 = (D_ * D_) / 4;
    round_copy<<<(nX4 + NTHREADS - 1) / NTHREADS, blk>>>(X, gX, nX4);
    round_copy<<<(nW4 + NTHREADS - 1) / NTHREADS, blk>>>(Wq, gW,            nW4);
    round_copy<<<(nW4 + NTHREADS - 1) / NTHREADS, blk>>>(Wk, gW + D_ * D_,  nW4);
    round_copy<<<(nW4 + NTHREADS - 1) / NTHREADS, blk>>>(Wv, gW + 2 * D_ * D_, nW4);

    // 1) QKV projections (V transposed+rounded on store)
    gemm_qkv<<<dim3(M_TOT / BM, D_ / BN, 3), blk, SMEM_BYTES>>>();

    // 2) causal scores
    gemm_scores<<<dim3(S_ / BN, S_ / BM, B_), blk, SMEM_BYTES>>>();

    // 3) softmax (rounds P)
    softmax_causal<<<dim3(S_, B_), blk>>>();

    // 4) P @ V
    gemm_pv<<<dim3(D_ / BN, S_ / BM, B_), blk, SMEM_BYTES>>>(Out);
}

// round 6
// speedup vs baseline: 4.4981x; 1.0245x over previous
#include <cuda_runtime.h>
#include <cstdint>

// Problem constants
#define B_    4
#define S_    2048
#define D_    1024
#define M_TOT (B_ * S_)

// Tiling
#define BM 128
#define BN 128
#define BKK 32                    // k per mainloop iter (4 mma k-steps of 8)
#define NTHREADS 256              // 8 warps: 4 (m32) x 2 (n64)
#define STAGES 3
#define STAGE_FLOATS 8192         // A(128x32) + B(128x32)
#define SMEM_BYTES (STAGES * STAGE_FLOATS * 4)   // 98304

// Scratch (tf32-prerounded operands live here)
__device__ float g_X [M_TOT * D_];
__device__ float g_W [3 * D_ * D_];
__device__ float g_Q [M_TOT * D_];
__device__ float g_K [M_TOT * D_];
__device__ float g_Vt[M_TOT * D_];           // rounded V, transposed [b][d][s]
__device__ float g_P [B_ * S_ * S_];

// ---------------------------------------------------------------------------
// PTX helpers
// ---------------------------------------------------------------------------
__device__ __forceinline__ uint32_t smem_u32(const void* p) {
    return (uint32_t)__cvta_generic_to_shared(p);
}
__device__ __forceinline__ uint32_t f2tf32(float f) {
    uint32_t r;
    asm("cvt.rna.tf32.f32 %0, %1;" : "=r"(r) : "f"(f));
    return r;
}
__device__ __forceinline__ float roundtf(float f) { return __uint_as_float(f2tf32(f)); }

__device__ __forceinline__ void ldsm_x4(uint32_t addr, uint32_t& r0, uint32_t& r1,
                                        uint32_t& r2, uint32_t& r3) {
    asm volatile("ldmatrix.sync.aligned.m8n8.x4.shared.b16 {%0,%1,%2,%3}, [%4];"
                 : "=r"(r0), "=r"(r1), "=r"(r2), "=r"(r3) : "r"(addr));
}
__device__ __forceinline__ void mma_tf32(float* c, const uint32_t* a,
                                         uint32_t b0, uint32_t b1) {
    asm volatile(
        "mma.sync.aligned.m16n8k8.row.col.f32.tf32.tf32.f32 "
        "{%0,%1,%2,%3}, {%4,%5,%6,%7}, {%8,%9}, {%0,%1,%2,%3};"
        : "+f"(c[0]), "+f"(c[1]), "+f"(c[2]), "+f"(c[3])
        : "r"(a[0]), "r"(a[1]), "r"(a[2]), "r"(a[3]), "r"(b0), "r"(b1));
}
__device__ __forceinline__ void cp16(uint32_t saddr, const float* g) {
    asm volatile("cp.async.cg.shared.global [%0], [%1], 16;" :: "r"(saddr), "l"(g));
}
__device__ __forceinline__ void cp_commit() { asm volatile("cp.async.commit_group;"); }
__device__ __forceinline__ void cp_wait1()  { asm volatile("cp.async.wait_group 1;"); }

// XOR-swizzled float offset within a [128][32] tile (16B chunk granularity).
__device__ __forceinline__ int swz(int r, int c) {
    return (r << 5) + (((c ^ (r & 7)) & 7) << 2);
}

// ---------------------------------------------------------------------------
// cp.async one stage: A tile [128][32] from gA (k-contig, ld ldA), B likewise.
// ---------------------------------------------------------------------------
__device__ __forceinline__
void issue_stage(const float* __restrict__ gA, const float* __restrict__ gB,
                 int ldA, int ldB, float* stage, int tid)
{
#pragma unroll
    for (int i = 0; i < 4; ++i) {
        int idx = tid + i * NTHREADS;       // 0..1023
        int r = idx >> 3, c = idx & 7;
        cp16(smem_u32(stage + swz(r, c)), gA + (size_t)r * ldA + c * 4);
    }
#pragma unroll
    for (int i = 0; i < 4; ++i) {
        int idx = tid + i * NTHREADS;
        int r = idx >> 3, c = idx & 7;
        cp16(smem_u32(stage + 4096 + swz(r, c)), gB + (size_t)r * ldB + c * 4);
    }
}

// ---------------------------------------------------------------------------
// Warp compute over one stage (4 mma k-steps), fragment-pipelined:
// A and B-low are double-buffered across k-steps; B-high loads hide under
// the B-low MMA block and the next B-low load hides under the B-high block.
// ---------------------------------------------------------------------------
__device__ __forceinline__
void warp_compute(const float* stage, int warp_m, int warp_n, int lane,
                  float acc[2][8][4])
{
    const float* As = stage;
    const float* Bs = stage + 4096;
    const int aR = warp_m * 32 + (lane & 15);
    const int aC = (lane >> 4);
    const int bR = warp_n * 64 + ((lane >> 4) << 3) + (lane & 7);
    const int bC = ((lane >> 3) & 1);

    uint32_t a[2][2][4];       // [buf][mt][frag]
    uint32_t blo[2][4][2];     // [buf][nt 0..3][frag]
    uint32_t bhi[4][2];        // [nt 4..7][frag]

    // Prologue (ks = 0): A frags + B-low half.
#pragma unroll
    for (int mt = 0; mt < 2; ++mt)
        ldsm_x4(smem_u32(As + swz(aR + mt * 16, aC)),
                a[0][mt][0], a[0][mt][1], a[0][mt][2], a[0][mt][3]);
#pragma unroll
    for (int np = 0; np < 2; ++np)
        ldsm_x4(smem_u32(Bs + swz(bR + np * 16, bC)),
                blo[0][2 * np][0], blo[0][2 * np][1],
                blo[0][2 * np + 1][0], blo[0][2 * np + 1][1]);

#pragma unroll
    for (int ks = 0; ks < 4; ++ks) {
        const int cur = ks & 1, nxt = cur ^ 1;

        // B-high for this ks (consumed after the B-low MMA block).
#pragma unroll
        for (int np = 2; np < 4; ++np)
            ldsm_x4(smem_u32(Bs + swz(bR + np * 16, ks * 2 + bC)),
                    bhi[2 * (np - 2)][0], bhi[2 * (np - 2)][1],
                    bhi[2 * (np - 2) + 1][0], bhi[2 * (np - 2) + 1][1]);
        // A for ks+1.
        if (ks < 3) {
#pragma unroll
            for (int mt = 0; mt < 2; ++mt)
                ldsm_x4(smem_u32(As + swz(aR + mt * 16, (ks + 1) * 2 + aC)),
                        a[nxt][mt][0], a[nxt][mt][1], a[nxt][mt][2], a[nxt][mt][3]);
        }
        // MMA block 1: B-low (loaded one phase earlier — latency hidden).
#pragma unroll
        for (int mt = 0; mt < 2; ++mt)
#pragma unroll
            for (int nt = 0; nt < 4; ++nt)
                mma_tf32(acc[mt][nt], a[cur][mt], blo[cur][nt][0], blo[cur][nt][1]);
        // B-low for ks+1 (hidden under MMA block 2).
        if (ks < 3) {
#pragma unroll
            for (int np = 0; np < 2; ++np)
                ldsm_x4(smem_u32(Bs + swz(bR + np * 16, (ks + 1) * 2 + bC)),
                        blo[nxt][2 * np][0], blo[nxt][2 * np][1],
                        blo[nxt][2 * np + 1][0], blo[nxt][2 * np + 1][1]);
        }
        // MMA block 2: B-high.
#pragma unroll
        for (int mt = 0; mt < 2; ++mt)
#pragma unroll
            for (int nt = 0; nt < 4; ++nt)
                mma_tf32(acc[mt][nt + 4], a[cur][mt], bhi[nt][0], bhi[nt][1]);
    }
}

// ---------------------------------------------------------------------------
// Pipelined mainloop: 3-stage cp.async, one sync per iter.
// ---------------------------------------------------------------------------
__device__ __forceinline__
void gemm_mainloop(const float* __restrict__ gA, const float* __restrict__ gB,
                   int ldA, int ldB, int niter, float* smem, int tid,
                   int warp_m, int warp_n, int lane, float acc[2][8][4])
{
    issue_stage(gA,      gB,      ldA, ldB, smem,                tid); cp_commit();
    issue_stage(gA + 32, gB + 32, ldA, ldB, smem + STAGE_FLOATS, tid); cp_commit();

    for (int i = 0; i < niter; ++i) {
        cp_wait1();
        __syncthreads();
        if (i + 2 < niter)
            issue_stage(gA + (size_t)(i + 2) * BKK, gB + (size_t)(i + 2) * BKK,
                        ldA, ldB, smem + ((i + 2) % STAGES) * STAGE_FLOATS, tid);
        cp_commit();
        warp_compute(smem + (i % STAGES) * STAGE_FLOATS, warp_m, warp_n, lane, acc);
    }
}

__device__ __forceinline__
void epilogue_plain(float* __restrict__ C, int ldc, int m0, int n0,
                    int warp_m, int warp_n, int lane,
                    const float acc[2][8][4], float alpha, bool roundOut)
{
    const int g = lane >> 2;
    const int c2 = (lane & 3) * 2;
#pragma unroll
    for (int mt = 0; mt < 2; ++mt) {
        int row = m0 + warp_m * 32 + mt * 16 + g;
#pragma unroll
        for (int nt = 0; nt < 8; ++nt) {
            int col = n0 + warp_n * 64 + nt * 8 + c2;
            float x0 = alpha * acc[mt][nt][0], x1 = alpha * acc[mt][nt][1];
            float x2 = alpha * acc[mt][nt][2], x3 = alpha * acc[mt][nt][3];
            if (roundOut) { x0 = roundtf(x0); x1 = roundtf(x1); x2 = roundtf(x2); x3 = roundtf(x3); }
            *(float2*)&C[(size_t)row * ldc + col]       = make_float2(x0, x1);
            *(float2*)&C[(size_t)(row + 8) * ldc + col] = make_float2(x2, x3);
        }
    }
}

// ---------------------------------------------------------------------------
// Kernel 0a: tf32 pre-round copy (single source).
// ---------------------------------------------------------------------------
__global__ __launch_bounds__(NTHREADS)
void round_copy(const float* __restrict__ src, float* __restrict__ dst, int n4)
{
    int i = blockIdx.x * NTHREADS + threadIdx.x;
    if (i < n4) {
        float4 v = ((const float4*)src)[i];
        v.x = roundtf(v.x); v.y = roundtf(v.y);
        v.z = roundtf(v.z); v.w = roundtf(v.w);
        ((float4*)dst)[i] = v;
    }
}

// Kernel 0b: round three equal-size sources into one contiguous destination.
__global__ __launch_bounds__(NTHREADS)
void round_copy3(const float* __restrict__ s0, const float* __restrict__ s1,
                 const float* __restrict__ s2, float* __restrict__ dst, int n4seg)
{
    int i = blockIdx.x * NTHREADS + threadIdx.x;
    if (i < 3 * n4seg) {
        int seg = i / n4seg, off = i - seg * n4seg;
        const float* s = (seg == 0) ? s0 : (seg == 1) ? s1 : s2;
        float4 v = ((const float4*)s)[off];
        v.x = roundtf(v.x); v.y = roundtf(v.y);
        v.z = roundtf(v.z); v.w = roundtf(v.w);
        ((float4*)dst)[i] = v;
    }
}

// ---------------------------------------------------------------------------
// Kernel 1: QKV projection (z selects W / output). Q,K stored rounded;
// V stored rounded AND transposed into g_Vt[b][d][s].
// ---------------------------------------------------------------------------
__global__ __launch_bounds__(NTHREADS, 2)
void gemm_qkv()
{
    extern __shared__ float smem[];
    const int z = blockIdx.z;
    const float* A = g_X;
    const float* Bm = g_W + (size_t)z * D_ * D_;

    const int m0 = blockIdx.x * BM;
    const int n0 = blockIdx.y * BN;
    const int tid = threadIdx.x;
    const int lane = tid & 31;
    const int w = tid >> 5;
    const int warp_m = w & 3, warp_n = w >> 2;

    float acc[2][8][4] = {};
    gemm_mainloop(A + (size_t)m0 * D_, Bm + (size_t)n0 * D_, D_, D_,
                  D_ / BKK, smem, tid, warp_m, warp_n, lane, acc);

    if (z < 2) {
        float* C = (z == 0) ? g_Q : g_K;
        epilogue_plain(C, D_, m0, n0, warp_m, warp_n, lane, acc, 1.0f, true);
    } else {
        const int g = lane >> 2;
        const int c2 = (lane & 3) * 2;
#pragma unroll
        for (int mt = 0; mt < 2; ++mt) {
            int row = m0 + warp_m * 32 + mt * 16 + g;
            int b = row >> 11, s = row & (S_ - 1);
            int s8 = s + 8;
#pragma unroll
            for (int nt = 0; nt < 8; ++nt) {
                int col = n0 + warp_n * 64 + nt * 8 + c2;
                size_t base0 = ((size_t)(b * D_ + col)) * S_;
                size_t base1 = ((size_t)(b * D_ + col + 1)) * S_;
                g_Vt[base0 + s]  = roundtf(acc[mt][nt][0]);
                g_Vt[base1 + s]  = roundtf(acc[mt][nt][1]);
                g_Vt[base0 + s8] = roundtf(acc[mt][nt][2]);
                g_Vt[base1 + s8] = roundtf(acc[mt][nt][3]);
            }
        }
    }
}

// ---------------------------------------------------------------------------
// Kernel 2: scores = (Q K^T)/sqrt(D), lower-triangular tiles only.
// ---------------------------------------------------------------------------
__global__ __launch_bounds__(NTHREADS, 2)
void gemm_scores()
{
    const int kt = blockIdx.x;
    const int qt = blockIdx.y;
    if (kt > qt) return;
    extern __shared__ float smem[];

    const int b = blockIdx.z;
    const float* Qb = g_Q + (size_t)b * (S_ * D_);
    const float* Kb = g_K + (size_t)b * (S_ * D_);
    float*       Cb = g_P + (size_t)b * (S_ * S_);

    const int m0 = qt * BM;
    const int n0 = kt * BN;
    const int tid = threadIdx.x;
    const int lane = tid & 31;
    const int w = tid >> 5;
    const int warp_m = w & 3, warp_n = w >> 2;

    float acc[2][8][4] = {};
    gemm_mainloop(Qb + (size_t)m0 * D_, Kb + (size_t)n0 * D_, D_, D_,
                  D_ / BKK, smem, tid, warp_m, warp_n, lane, acc);
    epilogue_plain(Cb, S_, m0, n0, warp_m, warp_n, lane, acc, 0.03125f, false);
}

// ---------------------------------------------------------------------------
// Kernel 3: causal row softmax; stores tf32-rounded probs. Writes only up to
// the 128-aligned diagonal boundary — exactly the range gemm_pv reads.
// ---------------------------------------------------------------------------
__global__ __launch_bounds__(NTHREADS)
void softmax_causal()
{
    const int q = blockIdx.x;
    const int b = blockIdx.y;
    float* row = g_P + (size_t)(b * S_ + q) * S_;
    const int len  = q + 1;
    const int wlen = (len + 127) & ~127;     // write extent (PV read extent)

    const int tid  = threadIdx.x;
    const int lane = tid & 31;
    const int wid  = tid >> 5;

    float v[8];
    float m = -3.0e38f;
#pragma unroll
    for (int j = 0; j < 8; ++j) {
        int idx = tid + j * NTHREADS;
        v[j] = (idx < len) ? row[idx] : -3.0e38f;
        m = fmaxf(m, v[j]);
    }
#pragma unroll
    for (int off = 16; off > 0; off >>= 1)
        m = fmaxf(m, __shfl_xor_sync(0xFFFFFFFFu, m, off));

    __shared__ float red[8];
    __shared__ float s_max, s_sum;
    if (lane == 0) red[wid] = m;
    __syncthreads();
    if (tid == 0) {
        float mm = red[0];
#pragma unroll
        for (int i = 1; i < 8; ++i) mm = fmaxf(mm, red[i]);
        s_max = mm;
    }
    __syncthreads();
    const float rmax = s_max;

    float s = 0.0f;
#pragma unroll
    for (int j = 0; j < 8; ++j) {
        int idx = tid + j * NTHREADS;
        float e = (idx < len) ? __expf(v[j] - rmax) : 0.0f;
        v[j] = e;
        s += e;
    }
#pragma unroll
    for (int off = 16; off > 0; off >>= 1)
        s += __shfl_xor_sync(0xFFFFFFFFu, s, off);
    if (lane == 0) red[wid] = s;
    __syncthreads();
    if (tid == 0) {
        float ss = 0.0f;
#pragma unroll
        for (int i = 0; i < 8; ++i) ss += red[i];
        s_sum = ss;
    }
    __syncthreads();
    const float inv = 1.0f / s_sum;

#pragma unroll
    for (int j = 0; j < 8; ++j) {
        int idx = tid + j * NTHREADS;
        if (idx < wlen) row[idx] = roundtf(v[j] * inv);
    }
}

// ---------------------------------------------------------------------------
// Kernel 4: Out = P @ Vt^T (NT form), k-loop up to the causal diagonal.
// ---------------------------------------------------------------------------
__global__ __launch_bounds__(NTHREADS, 2)
void gemm_pv(float* __restrict__ Out)
{
    extern __shared__ float smem[];
    const int nt = blockIdx.x;
    const int qt = blockIdx.y;
    const int b  = blockIdx.z;

    const float* Pb = g_P  + (size_t)b * (S_ * S_);
    const float* Vb = g_Vt + (size_t)b * (S_ * D_);   // [d][s]
    float*       Cb = Out  + (size_t)b * (S_ * D_);

    const int m0 = qt * BM;
    const int n0 = nt * BN;
    const int tid = threadIdx.x;
    const int lane = tid & 31;
    const int w = tid >> 5;
    const int warp_m = w & 3, warp_n = w >> 2;

    float acc[2][8][4] = {};
    const int niter = (qt + 1) * (BM / BKK);          // causal k extent
    gemm_mainloop(Pb + (size_t)m0 * S_, Vb + (size_t)n0 * S_, S_, S_,
                  niter, smem, tid, warp_m, warp_n, lane, acc);
    epilogue_plain(Cb, D_, m0, n0, warp_m, warp_n, lane, acc, 1.0f, false);
}

// ---------------------------------------------------------------------------
// Launch
// ---------------------------------------------------------------------------
extern "C" void kernel_launch(void* const* d_in, const int* in_sizes, int n_in,
                              void* d_out, int out_size)
{
    const float* X  = (const float*)d_in[0];
    const float* Wq = (const float*)d_in[1];
    const float* Wk = (const float*)d_in[2];
    const float* Wv = (const float*)d_in[3];
    float* Out = (float*)d_out;

    cudaFuncSetAttribute(gemm_qkv,    cudaFuncAttributeMaxDynamicSharedMemorySize, SMEM_BYTES);
    cudaFuncSetAttribute(gemm_scores, cudaFuncAttributeMaxDynamicSharedMemorySize, SMEM_BYTES);
    cudaFuncSetAttribute(gemm_pv,     cudaFuncAttributeMaxDynamicSharedMemorySize, SMEM_BYTES);

    dim3 blk(NTHREADS);

    // 0) pre-round inputs to tf32
    float* gX; cudaGetSymbolAddress((void**)&gX, g_X);
    float* gW; cudaGetSymbolAddress((void**)&gW, g_W);
    const int nX4 = (M_TOT * D_) / 4;
    const int nW4 = (D_ * D_) / 4;
    round_copy<<<(nX4 + NTHREADS - 1) / NTHREADS, blk>>>(X, gX, nX4);
    round_copy3<<<(3 * nW4 + NTHREADS - 1) / NTHREADS, blk>>>(Wq, Wk, Wv, gW, nW4);

    // 1) QKV projections (V transposed+rounded on store)
    gemm_qkv<<<dim3(M_TOT / BM, D_ / BN, 3), blk, SMEM_BYTES>>>();

    // 2) causal scores
    gemm_scores<<<dim3(S_ / BN, S_ / BM, B_), blk, SMEM_BYTES>>>();

    // 3) softmax (rounds P, writes only PV-visible extent)
    softmax_causal<<<dim3(S_, B_), blk>>>();

    // 4) P @ V
    gemm_pv<<<dim3(D_ / BN, S_ / BM, B_), blk, SMEM_BYTES>>>(Out);
}

// round 8
// speedup vs baseline: 8.2097x; 1.8251x over previous
#include <cuda_runtime.h>
#include <cuda_fp16.h>
#include <cstdint>

// Problem constants
#define B_    4
#define S_    2048
#define D_    1024
#define M_TOT (B_ * S_)

// Tiling (fp16 operands, fp32 accumulate)
#define BM 128
#define BN 128
#define BKK 64                    // k (halves) per mainloop iter = 4 mma k-steps of 16
#define NTHREADS 256              // 8 warps: 4 (m32) x 2 (n64)
#define STAGES 3
#define STAGE_HALVES 16384        // A(128x64h) + B(128x64h) = 16KB + 16KB
#define SMEM_BYTES (STAGES * STAGE_HALVES * 2)   // 98304

// Scratch
__device__ __align__(16) __half g_X [M_TOT * D_];
__device__ __align__(16) __half g_W [3 * D_ * D_];
__device__ __align__(16) __half g_Q [M_TOT * D_];
__device__ __align__(16) __half g_K [M_TOT * D_];
__device__ __align__(16) __half g_Vt[M_TOT * D_];     // V transposed [b][d][s]
__device__ float  g_P [B_ * S_ * S_];                 // raw scores (fp32!)
__device__ __align__(16) __half g_Ph[B_ * S_ * S_];   // fp16 probs

// ---------------------------------------------------------------------------
// PTX helpers
// ---------------------------------------------------------------------------
__device__ __forceinline__ uint32_t smem_u32(const void* p) {
    return (uint32_t)__cvta_generic_to_shared(p);
}
__device__ __forceinline__ void ldsm_x4(uint32_t addr, uint32_t& r0, uint32_t& r1,
                                        uint32_t& r2, uint32_t& r3) {
    asm volatile("ldmatrix.sync.aligned.m8n8.x4.shared.b16 {%0,%1,%2,%3}, [%4];"
                 : "=r"(r0), "=r"(r1), "=r"(r2), "=r"(r3) : "r"(addr));
}
__device__ __forceinline__ void mma_f16(float* c, const uint32_t* a,
                                        uint32_t b0, uint32_t b1) {
    asm volatile(
        "mma.sync.aligned.m16n8k16.row.col.f32.f16.f16.f32 "
        "{%0,%1,%2,%3}, {%4,%5,%6,%7}, {%8,%9}, {%0,%1,%2,%3};"
        : "+f"(c[0]), "+f"(c[1]), "+f"(c[2]), "+f"(c[3])
        : "r"(a[0]), "r"(a[1]), "r"(a[2]), "r"(a[3]), "r"(b0), "r"(b1));
}
__device__ __forceinline__ void cp16(uint32_t saddr, const void* g) {
    asm volatile("cp.async.cg.shared.global [%0], [%1], 16;" :: "r"(saddr), "l"(g));
}
__device__ __forceinline__ void cp_commit() { asm volatile("cp.async.commit_group;"); }
__device__ __forceinline__ void cp_wait1()  { asm volatile("cp.async.wait_group 1;"); }

// XOR-swizzled half offset within a [128][64h] tile (16B chunk = 8 halves).
__device__ __forceinline__ int swzh(int r, int c) {
    return (r << 6) + (((c ^ r) & 7) << 3);
}

// ---------------------------------------------------------------------------
// cp.async one stage: A tile [128][64h] (k-contig, ld in halves), B likewise.
// ---------------------------------------------------------------------------
__device__ __forceinline__
void issue_stage(const __half* __restrict__ gA, const __half* __restrict__ gB,
                 int ldA, int ldB, __half* stage, int tid)
{
#pragma unroll
    for (int i = 0; i < 4; ++i) {
        int idx = tid + i * NTHREADS;       // 0..1023
        int r = idx >> 3, c = idx & 7;
        cp16(smem_u32(stage + swzh(r, c)), gA + (size_t)r * ldA + c * 8);
    }
#pragma unroll
    for (int i = 0; i < 4; ++i) {
        int idx = tid + i * NTHREADS;
        int r = idx >> 3, c = idx & 7;
        cp16(smem_u32(stage + 8192 + swzh(r, c)), gB + (size_t)r * ldB + c * 8);
    }
}

// ---------------------------------------------------------------------------
// Warp compute over one stage: 4 k-steps of K=16, fragment-pipelined.
// ---------------------------------------------------------------------------
__device__ __forceinline__
void warp_compute(const __half* stage, int warp_m, int warp_n, int lane,
                  float acc[2][8][4])
{
    const __half* As = stage;
    const __half* Bs = stage + 8192;
    const int aR = warp_m * 32 + (lane & 15);
    const int aC = (lane >> 4);                           // k-chunk select (klo/khi)
    const int bR = warp_n * 64 + ((lane >> 4) << 3) + (lane & 7);
    const int bC = ((lane >> 3) & 1);

    uint32_t a[2][2][4];       // [buf][mt][frag]
    uint32_t blo[2][4][2];     // [buf][nt 0..3][frag]
    uint32_t bhi[4][2];        // [nt 4..7][frag]

    // Prologue (ks = 0)
#pragma unroll
    for (int mt = 0; mt < 2; ++mt)
        ldsm_x4(smem_u32(As + swzh(aR + mt * 16, aC)),
                a[0][mt][0], a[0][mt][1], a[0][mt][2], a[0][mt][3]);
#pragma unroll
    for (int np = 0; np < 2; ++np)
        ldsm_x4(smem_u32(Bs + swzh(bR + np * 16, bC)),
                blo[0][2 * np][0], blo[0][2 * np][1],
                blo[0][2 * np + 1][0], blo[0][2 * np + 1][1]);

#pragma unroll
    for (int ks = 0; ks < 4; ++ks) {
        const int cur = ks & 1, nxt = cur ^ 1;

#pragma unroll
        for (int np = 2; np < 4; ++np)
            ldsm_x4(smem_u32(Bs + swzh(bR + np * 16, ks * 2 + bC)),
                    bhi[2 * (np - 2)][0], bhi[2 * (np - 2)][1],
                    bhi[2 * (np - 2) + 1][0], bhi[2 * (np - 2) + 1][1]);
        if (ks < 3) {
#pragma unroll
            for (int mt = 0; mt < 2; ++mt)
                ldsm_x4(smem_u32(As + swzh(aR + mt * 16, (ks + 1) * 2 + aC)),
                        a[nxt][mt][0], a[nxt][mt][1], a[nxt][mt][2], a[nxt][mt][3]);
        }
#pragma unroll
        for (int mt = 0; mt < 2; ++mt)
#pragma unroll
            for (int nt = 0; nt < 4; ++nt)
                mma_f16(acc[mt][nt], a[cur][mt], blo[cur][nt][0], blo[cur][nt][1]);
        if (ks < 3) {
#pragma unroll
            for (int np = 0; np < 2; ++np)
                ldsm_x4(smem_u32(Bs + swzh(bR + np * 16, (ks + 1) * 2 + bC)),
                        blo[nxt][2 * np][0], blo[nxt][2 * np][1],
                        blo[nxt][2 * np + 1][0], blo[nxt][2 * np + 1][1]);
        }
#pragma unroll
        for (int mt = 0; mt < 2; ++mt)
#pragma unroll
            for (int nt = 0; nt < 4; ++nt)
                mma_f16(acc[mt][nt + 4], a[cur][mt], bhi[nt][0], bhi[nt][1]);
    }
}

// ---------------------------------------------------------------------------
// Pipelined mainloop: 3-stage cp.async, one sync per iter.
// ---------------------------------------------------------------------------
__device__ __forceinline__
void gemm_mainloop(const __half* __restrict__ gA, const __half* __restrict__ gB,
                   int ldA, int ldB, int niter, __half* smem, int tid,
                   int warp_m, int warp_n, int lane, float acc[2][8][4])
{
    issue_stage(gA,       gB,       ldA, ldB, smem,                tid); cp_commit();
    issue_stage(gA + BKK, gB + BKK, ldA, ldB, smem + STAGE_HALVES, tid); cp_commit();

    for (int i = 0; i < niter; ++i) {
        cp_wait1();
        __syncthreads();
        if (i + 2 < niter)
            issue_stage(gA + (size_t)(i + 2) * BKK, gB + (size_t)(i + 2) * BKK,
                        ldA, ldB, smem + ((i + 2) % STAGES) * STAGE_HALVES, tid);
        cp_commit();
        warp_compute(smem + (i % STAGES) * STAGE_HALVES, warp_m, warp_n, lane, acc);
    }
}

// fp32 epilogue (scores / final output)
__device__ __forceinline__
void epilogue_f32(float* __restrict__ C, int ldc, int m0, int n0,
                  int warp_m, int warp_n, int lane,
                  const float acc[2][8][4], float alpha)
{
    const int g = lane >> 2;
    const int c2 = (lane & 3) * 2;
#pragma unroll
    for (int mt = 0; mt < 2; ++mt) {
        int row = m0 + warp_m * 32 + mt * 16 + g;
#pragma unroll
        for (int nt = 0; nt < 8; ++nt) {
            int col = n0 + warp_n * 64 + nt * 8 + c2;
            *(float2*)&C[(size_t)row * ldc + col] =
                make_float2(alpha * acc[mt][nt][0], alpha * acc[mt][nt][1]);
            *(float2*)&C[(size_t)(row + 8) * ldc + col] =
                make_float2(alpha * acc[mt][nt][2], alpha * acc[mt][nt][3]);
        }
    }
}

// fp16 epilogue (Q / K)
__device__ __forceinline__
void epilogue_f16(__half* __restrict__ C, int ldc, int m0, int n0,
                  int warp_m, int warp_n, int lane, const float acc[2][8][4])
{
    const int g = lane >> 2;
    const int c2 = (lane & 3) * 2;
#pragma unroll
    for (int mt = 0; mt < 2; ++mt) {
        int row = m0 + warp_m * 32 + mt * 16 + g;
#pragma unroll
        for (int nt = 0; nt < 8; ++nt) {
            int col = n0 + warp_n * 64 + nt * 8 + c2;
            *(__half2*)&C[(size_t)row * ldc + col] =
                __floats2half2_rn(acc[mt][nt][0], acc[mt][nt][1]);
            *(__half2*)&C[(size_t)(row + 8) * ldc + col] =
                __floats2half2_rn(acc[mt][nt][2], acc[mt][nt][3]);
        }
    }
}

// ---------------------------------------------------------------------------
// Kernel 0: fp32 -> fp16 input conversion.
// ---------------------------------------------------------------------------
__global__ __launch_bounds__(NTHREADS)
void conv_h(const float* __restrict__ src, __half* __restrict__ dst, int n4)
{
    int i = blockIdx.x * NTHREADS + threadIdx.x;
    if (i < n4) {
        float4 v = ((const float4*)src)[i];
        ((__half2*)dst)[2 * i]     = __floats2half2_rn(v.x, v.y);
        ((__half2*)dst)[2 * i + 1] = __floats2half2_rn(v.z, v.w);
    }
}
__global__ __launch_bounds__(NTHREADS)
void conv_h3(const float* __restrict__ s0, const float* __restrict__ s1,
             const float* __restrict__ s2, __half* __restrict__ dst, int n4seg)
{
    int i = blockIdx.x * NTHREADS + threadIdx.x;
    if (i < 3 * n4seg) {
        int seg = i / n4seg, off = i - seg * n4seg;
        const float* s = (seg == 0) ? s0 : (seg == 1) ? s1 : s2;
        float4 v = ((const float4*)s)[off];
        ((__half2*)dst)[2 * i]     = __floats2half2_rn(v.x, v.y);
        ((__half2*)dst)[2 * i + 1] = __floats2half2_rn(v.z, v.w);
    }
}

// ---------------------------------------------------------------------------
// Kernel 1: QKV projection. Q,K -> fp16; V -> fp16 transposed g_Vt[b][d][s].
// ---------------------------------------------------------------------------
__global__ __launch_bounds__(NTHREADS, 2)
void gemm_qkv()
{
    extern __shared__ __half smem[];
    const int z = blockIdx.z;
    const __half* Bm = g_W + (size_t)z * D_ * D_;

    const int m0 = blockIdx.x * BM;
    const int n0 = blockIdx.y * BN;
    const int tid = threadIdx.x;
    const int lane = tid & 31;
    const int w = tid >> 5;
    const int warp_m = w & 3, warp_n = w >> 2;

    float acc[2][8][4] = {};
    gemm_mainloop(g_X + (size_t)m0 * D_, Bm + (size_t)n0 * D_, D_, D_,
                  D_ / BKK, smem, tid, warp_m, warp_n, lane, acc);

    if (z < 2) {
        epilogue_f16((z == 0) ? g_Q : g_K, D_, m0, n0, warp_m, warp_n, lane, acc);
    } else {
        const int g = lane >> 2;
        const int c2 = (lane & 3) * 2;
#pragma unroll
        for (int mt = 0; mt < 2; ++mt) {
            int row = m0 + warp_m * 32 + mt * 16 + g;
            int b = row >> 11, s = row & (S_ - 1);
            int s8 = s + 8;
#pragma unroll
            for (int nt = 0; nt < 8; ++nt) {
                int col = n0 + warp_n * 64 + nt * 8 + c2;
                size_t base0 = ((size_t)(b * D_ + col)) * S_;
                size_t base1 = ((size_t)(b * D_ + col + 1)) * S_;
                g_Vt[base0 + s]  = __float2half_rn(acc[mt][nt][0]);
                g_Vt[base1 + s]  = __float2half_rn(acc[mt][nt][1]);
                g_Vt[base0 + s8] = __float2half_rn(acc[mt][nt][2]);
                g_Vt[base1 + s8] = __float2half_rn(acc[mt][nt][3]);
            }
        }
    }
}

// ---------------------------------------------------------------------------
// Kernel 2: scores = (Q K^T)/sqrt(D) -> fp32 g_P. Lower-triangular tiles only.
// ---------------------------------------------------------------------------
__global__ __launch_bounds__(NTHREADS, 2)
void gemm_scores()
{
    const int kt = blockIdx.x;
    const int qt = blockIdx.y;
    if (kt > qt) return;
    extern __shared__ __half smem[];

    const int b = blockIdx.z;
    const __half* Qb = g_Q + (size_t)b * (S_ * D_);
    const __half* Kb = g_K + (size_t)b * (S_ * D_);
    float*        Cb = g_P + (size_t)b * (S_ * S_);

    const int m0 = qt * BM;
    const int n0 = kt * BN;
    const int tid = threadIdx.x;
    const int lane = tid & 31;
    const int w = tid >> 5;
    const int warp_m = w & 3, warp_n = w >> 2;

    float acc[2][8][4] = {};
    gemm_mainloop(Qb + (size_t)m0 * D_, Kb + (size_t)n0 * D_, D_, D_,
                  D_ / BKK, smem, tid, warp_m, warp_n, lane, acc);
    epilogue_f32(Cb, S_, m0, n0, warp_m, warp_n, lane, acc, 0.03125f);
}

// ---------------------------------------------------------------------------
// Kernel 3: causal row softmax: fp32 scores -> fp16 probs (g_Ph), writes only
// up to the 128-aligned diagonal boundary (PV read extent), zero tail.
// ---------------------------------------------------------------------------
__global__ __launch_bounds__(NTHREADS)
void softmax_causal()
{
    const int q = blockIdx.x;
    const int b = blockIdx.y;
    const float* row  = g_P  + (size_t)(b * S_ + q) * S_;
    __half*      rowh = g_Ph + (size_t)(b * S_ + q) * S_;
    const int len  = q + 1;
    const int wlen = (len + 127) & ~127;

    const int tid  = threadIdx.x;
    const int lane = tid & 31;
    const int wid  = tid >> 5;

    float v[8];
    float m = -3.0e38f;
#pragma unroll
    for (int j = 0; j < 8; ++j) {
        int idx = tid + j * NTHREADS;
        v[j] = (idx < len) ? row[idx] : -3.0e38f;
        m = fmaxf(m, v[j]);
    }
#pragma unroll
    for (int off = 16; off > 0; off >>= 1)
        m = fmaxf(m, __shfl_xor_sync(0xFFFFFFFFu, m, off));

    __shared__ float red[8];
    __shared__ float s_max, s_sum;
    if (lane == 0) red[wid] = m;
    __syncthreads();
    if (tid == 0) {
        float mm = red[0];
#pragma unroll
        for (int i = 1; i < 8; ++i) mm = fmaxf(mm, red[i]);
        s_max = mm;
    }
    __syncthreads();
    const float rmax = s_max;

    float s = 0.0f;
#pragma unroll
    for (int j = 0; j < 8; ++j) {
        int idx = tid + j * NTHREADS;
        float e = (idx < len) ? __expf(v[j] - rmax) : 0.0f;
        v[j] = e;
        s += e;
    }
#pragma unroll
    for (int off = 16; off > 0; off >>= 1)
        s += __shfl_xor_sync(0xFFFFFFFFu, s, off);
    if (lane == 0) red[wid] = s;
    __syncthreads();
    if (tid == 0) {
        float ss = 0.0f;
#pragma unroll
        for (int i = 0; i < 8; ++i) ss += red[i];
        s_sum = ss;
    }
    __syncthreads();
    const float inv = 1.0f / s_sum;

#pragma unroll
    for (int j = 0; j < 8; ++j) {
        int idx = tid + j * NTHREADS;
        if (idx < wlen) rowh[idx] = __float2half_rn(v[j] * inv);
    }
}

// ---------------------------------------------------------------------------
// Kernel 4: Out = P @ Vt^T (NT, fp16 in / fp32 out). Heavy q-tiles first.
// ---------------------------------------------------------------------------
__global__ __launch_bounds__(NTHREADS, 2)
void gemm_pv(float* __restrict__ Out)
{
    extern __shared__ __half smem[];
    const int nt = blockIdx.x;
    const int qt = gridDim.y - 1 - blockIdx.y;   // heavy tiles launch first
    const int b  = blockIdx.z;

    const __half* Pb = g_Ph + (size_t)b * (S_ * S_);
    const __half* Vb = g_Vt + (size_t)b * (S_ * D_);
    float*        Cb = Out  + (size_t)b * (S_ * D_);

    const int m0 = qt * BM;
    const int n0 = nt * BN;
    const int tid = threadIdx.x;
    const int lane = tid & 31;
    const int w = tid >> 5;
    const int warp_m = w & 3, warp_n = w >> 2;

    float acc[2][8][4] = {};
    const int niter = (qt + 1) * (BM / BKK);     // causal k extent
    gemm_mainloop(Pb + (size_t)m0 * S_, Vb + (size_t)n0 * S_, S_, S_,
                  niter, smem, tid, warp_m, warp_n, lane, acc);
    epilogue_f32(Cb, D_, m0, n0, warp_m, warp_n, lane, acc, 1.0f);
}

// ---------------------------------------------------------------------------
// Launch
// ---------------------------------------------------------------------------
extern "C" void kernel_launch(void* const* d_in, const int* in_sizes, int n_in,
                              void* d_out, int out_size)
{
    const float* X  = (const float*)d_in[0];
    const float* Wq = (const float*)d_in[1];
    const float* Wk = (const float*)d_in[2];
    const float* Wv = (const float*)d_in[3];
    float* Out = (float*)d_out;

    cudaFuncSetAttribute(gemm_qkv,    cudaFuncAttributeMaxDynamicSharedMemorySize, SMEM_BYTES);
    cudaFuncSetAttribute(gemm_scores, cudaFuncAttributeMaxDynamicSharedMemorySize, SMEM_BYTES);
    cudaFuncSetAttribute(gemm_pv,     cudaFuncAttributeMaxDynamicSharedMemorySize, SMEM_BYTES);

    dim3 blk(NTHREADS);

    // 0) convert inputs to fp16
    __half* gX; cudaGetSymbolAddress((void**)&gX, g_X);
    __half* gW; cudaGetSymbolAddress((void**)&gW, g_W);
    const int nX4 = (M_TOT * D_) / 4;
    const int nW4 = (D_ * D_) / 4;
    conv_h<<<(nX4 + NTHREADS - 1) / NTHREADS, blk>>>(X, gX, nX4);
    conv_h3<<<(3 * nW4 + NTHREADS - 1) / NTHREADS, blk>>>(Wq, Wk, Wv, gW, nW4);

    // 1) QKV projections
    gemm_qkv<<<dim3(M_TOT / BM, D_ / BN, 3), blk, SMEM_BYTES>>>();

    // 2) causal scores (fp32)
    gemm_scores<<<dim3(S_ / BN, S_ / BM, B_), blk, SMEM_BYTES>>>();

    // 3) softmax -> fp16 probs
    softmax_causal<<<dim3(S_, B_), blk>>>();

    // 4) P @ V
    gemm_pv<<<dim3(D_ / BN, S_ / BM, B_), blk, SMEM_BYTES>>>(Out);
}